// round 13
// baseline (speedup 1.0000x reference)
#include <cuda_runtime.h>
#include <cstdint>

// ---------------------------------------------------------------------------
// PConvLinear, fp16 mma.sync m16n8k16 both stages, cp.async gather.
//   out[p,o] = bias[o] + sum_f P[p,f] * W[o,f],  f = c*16 + m
//   P[p, c*16+m] = sum_{k<16} feat[p,k,c] * wn[p,k,m]
// prep_xin16: xin fp32 -> fp16 once; gather = cp.async 16B (no cvt, no regs).
// A tiles [k 16][c 16] fp16 (512B/pt), pconv via ldmatrix.trans.
// Main GEMM runs 67 real s-steps (padding work eliminated).
// 256 thr / 64 pts / 8 warps, 2 CTAs/SM, R11 schedule (2 syncs/group).
// ---------------------------------------------------------------------------

#define NPTS 120000
#define NB   60000
#define TPB  64
#define THREADS 256
#define GRID (NPTS / TPB)      // 1875

#define PROWB 528
#define OFF_A    33792         // after P buffer (64 x 528)
#define OFF_IND  66560         // + 64*512 A tiles
#define OFF_BIAS 70656
#define SMEM_BYTES 71168       // -> 2 CTAs/SM easily

// W fragments: [fs 80(+1 pad)][wn4 4][q*128 + l*4]
__device__ uint32_t Wfrag[81 * 1024];
// xin pre-converted to fp16: 120000 pts x 64 ch x 2B = 128B/pt
__device__ __align__(16) uint32_t xin16[120000 * 32];

__device__ __forceinline__ uint32_t smem_u32(const void* p) {
    uint32_t a;
    asm("{ .reg .u64 t; cvta.to.shared.u64 t, %1; cvt.u32.u64 %0, t; }"
        : "=r"(a) : "l"(p));
    return a;
}
__device__ __forceinline__ uint32_t pack_f16x2(float lo, float hi) {
    uint32_t r;
    asm("cvt.rn.f16x2.f32 %0, %1, %2;" : "=r"(r) : "f"(hi), "f"(lo));
    return r;
}
__device__ __forceinline__ void ldsm4(uint32_t r[4], uint32_t addr) {
    asm volatile("ldmatrix.sync.aligned.m8n8.x4.shared.b16 {%0,%1,%2,%3}, [%4];"
                 : "=r"(r[0]), "=r"(r[1]), "=r"(r[2]), "=r"(r[3]) : "r"(addr));
}
__device__ __forceinline__ void ldsm4t(uint32_t r[4], uint32_t addr) {
    asm volatile("ldmatrix.sync.aligned.m8n8.x4.trans.shared.b16 {%0,%1,%2,%3}, [%4];"
                 : "=r"(r[0]), "=r"(r[1]), "=r"(r[2]), "=r"(r[3]) : "r"(addr));
}
__device__ __forceinline__ void mma16(float c[4], const uint32_t a[4],
                                      uint32_t b0, uint32_t b1) {
    asm volatile(
        "mma.sync.aligned.m16n8k16.row.col.f32.f16.f16.f32 "
        "{%0,%1,%2,%3}, {%4,%5,%6,%7}, {%8,%9}, {%0,%1,%2,%3};"
        : "+f"(c[0]), "+f"(c[1]), "+f"(c[2]), "+f"(c[3])
        : "r"(a[0]), "r"(a[1]), "r"(a[2]), "r"(a[3]), "r"(b0), "r"(b1));
}
#define CP_ASYNC16(dst, src) \
    asm volatile("cp.async.ca.shared.global [%0], [%1], 16;" \
                 :: "r"(dst), "l"(src) : "memory")
#define CP_COMMIT() asm volatile("cp.async.commit_group;" ::: "memory")
#define CP_WAIT0()  asm volatile("cp.async.wait_group 0;" ::: "memory")

// ---- prep 1: analytic fp16 B fragments of W (proven) ----
extern "C" __global__ void __launch_bounds__(128, 1)
prep_kernel(const float* __restrict__ W) {
    const int bg = blockIdx.x;           // fs = g*16 + s
    const int t = threadIdx.x, l = t & 31, wn4 = t >> 5;
    const int f0 = (bg >> 4) * 256 + (bg & 15) * 16 + 2 * (l & 3);
    uint32_t r[8];
    #pragma unroll
    for (int nt = 0; nt < 4; ++nt) {
        int o = wn4 * 32 + nt * 8 + (l >> 2);
        const float* wr = W + (size_t)o * 1072;
        float v0 = (f0     < 1072) ? wr[f0]     : 0.f;
        float v1 = (f0 + 1 < 1072) ? wr[f0 + 1] : 0.f;
        float v2 = (f0 + 8 < 1072) ? wr[f0 + 8] : 0.f;
        float v3 = (f0 + 9 < 1072) ? wr[f0 + 9] : 0.f;
        r[nt * 2 + 0] = pack_f16x2(v0, v1);
        r[nt * 2 + 1] = pack_f16x2(v2, v3);
    }
    uint32_t* dst = Wfrag + (bg * 4 + wn4) * 256 + l * 4;
    *(uint4*)dst         = make_uint4(r[0], r[1], r[2], r[3]);
    *(uint4*)(dst + 128) = make_uint4(r[4], r[5], r[6], r[7]);
}

// ---- prep 2: xin fp32 -> fp16 ----
extern "C" __global__ void __launch_bounds__(256, 4)
prep_xin16(const float* __restrict__ xin) {
    int i = blockIdx.x * 256 + threadIdx.x;          // 1.92M float4s
    float4 v = *(const float4*)(xin + (size_t)i * 4);
    ((uint2*)xin16)[i] = make_uint2(pack_f16x2(v.x, v.y), pack_f16x2(v.z, v.w));
}

// ---- main ----
extern "C" __global__ void __launch_bounds__(THREADS, 2)
pcl_kernel(const int*   __restrict__ nbr,   // [2,60000,16]
           const float* __restrict__ wng,   // [2,60000,16,16]
           const float* __restrict__ addf,  // [2,60000,16,3]
           const float* __restrict__ bias,  // [128]
           float*       __restrict__ out)   // [2,60000,128]
{
    extern __shared__ __align__(16) char smc[];
    int*   inds = (int*)(smc + OFF_IND);
    float* bsm  = (float*)(smc + OFF_BIAS);

    const uint32_t smb = smem_u32(smc);
    const int t    = threadIdx.x;
    const int wid  = t >> 5;
    const int l    = t & 31;
    const int base = blockIdx.x * TPB;

    const int wm  = wid & 1;            // main-GEMM warp grid 2(m) x 4(n)
    const int wn4 = wid >> 1;

    if (t < 128) bsm[t] = bias[t];

    // ---- neighbor indices: 64 pts x 16 ----
    {
        int pt = base + (t >> 2);
        ((int4*)inds)[t] = *(const int4*)(nbr + (size_t)pt * 16 + (size_t)(t & 3) * 4);
    }
    __syncthreads();

    // ---- cp.async gather of group gt (0..3) into A [k][c] tiles ----
    auto gatherCP = [&](int gt) {
        const char* xb = (const char*)xin16;
        #pragma unroll
        for (int rep = 0; rep < 4; ++rep) {
            int v  = rep * 256 + t;
            int pp = v & 63, kk = v >> 6;
            int pid  = base + pp;
            int nb   = inds[pp * 16 + kk];
            int brow = (pid >= NB) ? NB : 0;
            const char* src = xb + (size_t)(brow + nb) * 128 + gt * 32;
            uint32_t dst = smb + OFF_A + pp * 512 + kk * 32;
            CP_ASYNC16(dst, src);
            CP_ASYNC16(dst + 16, src + 16);
        }
        CP_COMMIT();
    };
    // ---- scalar fill of group 4 (addf channels 0-2, rest zero) ----
    auto gatherAdd = [&]() {
        int pp  = t & 63;
        int q   = t >> 6;                 // 4 k-rows per thread
        int pid = base + pp;
        #pragma unroll
        for (int j = 0; j < 4; ++j) {
            int kk = q * 4 + j;
            const float* a = addf + ((size_t)pid * 16 + kk) * 3;
            uint4* dst = (uint4*)(smc + OFF_A + pp * 512 + kk * 32);
            dst[0] = make_uint4(pack_f16x2(a[0], a[1]), pack_f16x2(a[2], 0.f), 0, 0);
            dst[1] = make_uint4(0, 0, 0, 0);
        }
    };

    gatherCP(0);

    // ---- pconv B fragments: warp's 8 points from wng (overlaps cp.async) ----
    uint32_t bw[8][2][2];
    {
        const int c2 = 2 * (l & 3);
        const int nl = l >> 2;
        #pragma unroll
        for (int j = 0; j < 8; ++j) {
            const float* wp = wng + (size_t)(base + wid * 8 + j) * 256;
            #pragma unroll
            for (int h = 0; h < 2; ++h) {
                int m = h * 8 + nl;
                bw[j][h][0] = pack_f16x2(wp[c2 * 16 + m],       wp[(c2 + 1) * 16 + m]);
                bw[j][h][1] = pack_f16x2(wp[(c2 + 8) * 16 + m], wp[(c2 + 9) * 16 + m]);
            }
        }
    }

    float acc[2][4][4];
    #pragma unroll
    for (int i = 0; i < 2; ++i)
        #pragma unroll
        for (int j = 0; j < 4; ++j)
            #pragma unroll
            for (int q = 0; q < 4; ++q) acc[i][j][q] = 0.f;

    CP_WAIT0();
    __syncthreads();   // A(0) ready

    // role constants
    const uint32_t aoffT = (uint32_t)((((l >> 4) * 8 + (l & 7)) * 32)
                                      + (((l >> 3) & 1) * 16));  // ldsm.trans
    const int rr = l >> 2;               // pconv STS f-row
    const int mc = 2 * (l & 3);
    const uint32_t arow = smb + (uint32_t)((wm * 32 + (l & 15)) * PROWB
                                           + (l >> 4) * 16);     // GEMM A addr

    for (int g = 0; g < 5; ++g) {
        // ---- pconv(g): per warp 8 points; ldsm.trans + 2 MMA + 4 STS ----
        #pragma unroll
        for (int j = 0; j < 8; ++j) {
            int ptl = wid * 8 + j;
            uint32_t a[4];
            ldsm4t(a, smb + OFF_A + (uint32_t)(ptl * 512) + aoffT);
            char* prow = smc + ptl * PROWB;
            #pragma unroll
            for (int h = 0; h < 2; ++h) {
                float c[4] = {0.f, 0.f, 0.f, 0.f};
                mma16(c, a, bw[j][h][0], bw[j][h][1]);
                int fl = rr * 16 + h * 8 + mc;
                *(uint32_t*)(prow + fl * 2)         = pack_f16x2(c[0], c[1]);
                *(uint32_t*)(prow + (fl + 128) * 2) = pack_f16x2(c[2], c[3]);
            }
        }
        __syncthreads();   // P ready; A free

        // ---- issue gather(g+1) (async; overlaps whole GEMM) ----
        if (g < 3)       gatherCP(g + 1);
        else if (g == 3) gatherAdd();

        // ---- main GEMM(g): real s-steps only (g==4 -> 3) ----
        {
            const int nsteps = (g == 4) ? 3 : 16;
            const uint32_t* wfg = Wfrag + (size_t)(g * 16) * 1024 + wn4 * 256 + l * 4;
            uint4 u0c = *(const uint4*)wfg;
            uint4 u1c = *(const uint4*)(wfg + 128);
            for (int s = 0; s < nsteps; ++s) {
                const uint32_t* wfn = wfg + (size_t)(s + 1) * 1024;  // padded
                uint4 u0n = *(const uint4*)wfn;
                uint4 u1n = *(const uint4*)(wfn + 128);
                #pragma unroll
                for (int mt = 0; mt < 2; ++mt) {
                    uint32_t a[4];
                    ldsm4(a, arow + (uint32_t)(mt * 16 * PROWB + s * 32));
                    mma16(acc[mt][0], a, u0c.x, u0c.y);
                    mma16(acc[mt][1], a, u0c.z, u0c.w);
                    mma16(acc[mt][2], a, u1c.x, u1c.y);
                    mma16(acc[mt][3], a, u1c.z, u1c.w);
                }
                u0c = u0n; u1c = u1n;
            }
        }
        CP_WAIT0();
        __syncthreads();   // A(g+1) ready; P free
    }

    // ---- epilogue: bias + store (each warp 32p x 32o) ----
    #pragma unroll
    for (int mt = 0; mt < 2; ++mt) {
        int r = wm * 32 + mt * 16 + (l >> 2);
        #pragma unroll
        for (int nt = 0; nt < 4; ++nt) {
            int o  = wn4 * 32 + nt * 8 + 2 * (l & 3);
            float b0 = bsm[o], b1 = bsm[o + 1];
            int pid = base + r;
            *(float2*)(out + (size_t)pid * 128 + o) =
                make_float2(acc[mt][nt][0] + b0, acc[mt][nt][1] + b1);
            *(float2*)(out + (size_t)(pid + 8) * 128 + o) =
                make_float2(acc[mt][nt][2] + b0, acc[mt][nt][3] + b1);
        }
    }
}

extern "C" void kernel_launch(void* const* d_in, const int* in_sizes, int n_in,
                              void* d_out, int out_size) {
    const float* xin  = (const float*)d_in[0];
    const int*   nbr  = (const int*)d_in[1];
    const float* wng  = (const float*)d_in[2];
    const float* addf = (const float*)d_in[3];
    const float* W    = (const float*)d_in[4];
    const float* bias = (const float*)d_in[5];
    float*       out  = (float*)d_out;

    cudaFuncSetAttribute(pcl_kernel,
                         cudaFuncAttributeMaxDynamicSharedMemorySize, SMEM_BYTES);

    prep_kernel<<<80, 128>>>(W);
    prep_xin16<<<7500, 256>>>(xin);
    pcl_kernel<<<GRID, THREADS, SMEM_BYTES>>>(nbr, wng, addf, bias, out);
}

// round 14
// speedup vs baseline: 1.2381x; 1.2381x over previous
#include <cuda_runtime.h>
#include <cstdint>

// ---------------------------------------------------------------------------
// PConvLinear, both stages on fp16 mma.sync (m16n8k16), fp32 accumulate.
//   out[p,o] = bias[o] + sum_f P[p,f] * W[o,f],  f = c*16 + m
//   P[p, c*16+m] = sum_{k<16} feat[p,k,c] * wn[p,k,m]
// R14: R11 schedule + Wfrag prefetch distance 2 (rolling u[2] slots carried
// across group boundaries; Wfrag contiguous in fs) + padded-work trim
// (group 4 runs 3 real s-steps). Gather interleaved per 2 s-steps.
// ---------------------------------------------------------------------------

#define NPTS 120000
#define NB   60000
#define TPB  64
#define THREADS 256
#define GRID (NPTS / TPB)      // 1875

// smem byte offsets (R10/R11 proven layout)
#define OFF_P    0             // 64 rows x 528 B   (P tile)
#define OFF_A    33792         // 64 pts x 768 B    (feat tiles, 16r x 48B)
#define OFF_IND  82944         // 1024 ints
#define OFF_BIAS 87040         // 128 floats
#define SMEM_BYTES 87552       // -> 2 CTAs/SM

#define PROWB 528
#define AROWB 48
#define APTB  768

// W fragments: [fs 80][wn4 4][q*128 + l*4]
__device__ uint32_t Wfrag[80 * 1024];

__device__ __forceinline__ uint32_t smem_u32(const void* p) {
    uint32_t a;
    asm("{ .reg .u64 t; cvta.to.shared.u64 t, %1; cvt.u32.u64 %0, t; }"
        : "=r"(a) : "l"(p));
    return a;
}
__device__ __forceinline__ uint32_t pack_f16x2(float lo, float hi) {
    uint32_t r;
    asm("cvt.rn.f16x2.f32 %0, %1, %2;" : "=r"(r) : "f"(hi), "f"(lo));
    return r;
}
__device__ __forceinline__ void ldsm4(uint32_t r[4], uint32_t addr) {
    asm volatile("ldmatrix.sync.aligned.m8n8.x4.shared.b16 {%0,%1,%2,%3}, [%4];"
                 : "=r"(r[0]), "=r"(r[1]), "=r"(r[2]), "=r"(r[3]) : "r"(addr));
}
__device__ __forceinline__ void mma16(float c[4], const uint32_t a[4],
                                      uint32_t b0, uint32_t b1) {
    asm volatile(
        "mma.sync.aligned.m16n8k16.row.col.f32.f16.f16.f32 "
        "{%0,%1,%2,%3}, {%4,%5,%6,%7}, {%8,%9}, {%0,%1,%2,%3};"
        : "+f"(c[0]), "+f"(c[1]), "+f"(c[2]), "+f"(c[3])
        : "r"(a[0]), "r"(a[1]), "r"(a[2]), "r"(a[3]), "r"(b0), "r"(b1));
}

// ---- prep: analytic fp16 B fragments of W (proven) ----
extern "C" __global__ void __launch_bounds__(128, 1)
prep_kernel(const float* __restrict__ W) {
    const int bg = blockIdx.x;           // fs = g*16 + s
    const int t = threadIdx.x, l = t & 31, wn4 = t >> 5;
    const int f0 = (bg >> 4) * 256 + (bg & 15) * 16 + 2 * (l & 3);
    uint32_t r[8];
    #pragma unroll
    for (int nt = 0; nt < 4; ++nt) {
        int o = wn4 * 32 + nt * 8 + (l >> 2);
        const float* wr = W + (size_t)o * 1072;
        float v0 = (f0     < 1072) ? wr[f0]     : 0.f;
        float v1 = (f0 + 1 < 1072) ? wr[f0 + 1] : 0.f;
        float v2 = (f0 + 8 < 1072) ? wr[f0 + 8] : 0.f;
        float v3 = (f0 + 9 < 1072) ? wr[f0 + 9] : 0.f;
        r[nt * 2 + 0] = pack_f16x2(v0, v1);
        r[nt * 2 + 1] = pack_f16x2(v2, v3);
    }
    uint32_t* dst = Wfrag + (bg * 4 + wn4) * 256 + l * 4;
    *(uint4*)dst         = make_uint4(r[0], r[1], r[2], r[3]);
    *(uint4*)(dst + 128) = make_uint4(r[4], r[5], r[6], r[7]);
}

// ---- main ----
extern "C" __global__ void __launch_bounds__(THREADS, 2)
pcl_kernel(const float* __restrict__ xin,   // [2,60000,64]
           const int*   __restrict__ nbr,   // [2,60000,16]
           const float* __restrict__ wng,   // [2,60000,16,16]
           const float* __restrict__ addf,  // [2,60000,16,3]
           const float* __restrict__ bias,  // [128]
           float*       __restrict__ out)   // [2,60000,128]
{
    extern __shared__ __align__(16) char smc[];
    int*   inds = (int*)(smc + OFF_IND);
    float* bsm  = (float*)(smc + OFF_BIAS);

    const uint32_t smb = smem_u32(smc);
    const int t    = threadIdx.x;
    const int wid  = t >> 5;
    const int l    = t & 31;
    const int base = blockIdx.x * TPB;

    // main-GEMM roles
    const int wm  = wid & 1;
    const int wn4 = wid >> 1;

    if (t < 128) bsm[t] = bias[t];

    // ---- neighbor indices: 64 pts x 16 ----
    {
        int pt = base + (t >> 2);
        ((int4*)inds)[t] = *(const int4*)(nbr + (size_t)pt * 16 + (size_t)(t & 3) * 4);
    }

    // ---- pconv B fragments: warp's 8 points, per m-half, from wng ----
    uint32_t bw[8][2][2];
    {
        const int c2 = 2 * (l & 3);
        const int nl = l >> 2;
        #pragma unroll
        for (int j = 0; j < 8; ++j) {
            const float* wp = wng + (size_t)(base + wid * 8 + j) * 256;
            #pragma unroll
            for (int h = 0; h < 2; ++h) {
                int m = h * 8 + nl;
                bw[j][h][0] = pack_f16x2(wp[c2 * 16 + m],       wp[(c2 + 1) * 16 + m]);
                bw[j][h][1] = pack_f16x2(wp[(c2 + 8) * 16 + m], wp[(c2 + 9) * 16 + m]);
            }
        }
    }

    float acc[2][4][4];
    #pragma unroll
    for (int i = 0; i < 2; ++i)
        #pragma unroll
        for (int j = 0; j < 4; ++j)
            #pragma unroll
            for (int q = 0; q < 4; ++q) acc[i][j][q] = 0.f;

    // gather roles (fixed)
    const int gw  = t & 3;
    const int gkp = (t >> 2) & 7;
    const int gp8 = t >> 5;

    auto gatherLDG = [&](int gg, int rep, float4& va, float4& vb) {
        int pp  = rep * 8 + gp8;
        int pid = base + pp;
        if (gg < 4) {
            int k0   = 2 * gkp;
            int nb0  = inds[pp * 16 + k0];
            int nb1  = inds[pp * 16 + k0 + 1];
            int brow = (pid >= NB) ? NB : 0;
            va = *(const float4*)(xin + (size_t)(brow + nb0) * 64 + gg * 16 + gw * 4);
            vb = *(const float4*)(xin + (size_t)(brow + nb1) * 64 + gg * 16 + gw * 4);
        } else {
            va = make_float4(0.f, 0.f, 0.f, 0.f);
            vb = make_float4(0.f, 0.f, 0.f, 0.f);
            if (gw == 0) {
                const float* a0 = addf + ((size_t)pid * 16 + 2 * gkp) * 3;
                va.x = a0[0]; va.y = a0[1]; va.z = a0[2];
                vb.x = a0[3]; vb.y = a0[4]; vb.z = a0[5];
            }
        }
    };
    auto gatherSTS = [&](int rep, const float4& va, const float4& vb) {
        int pp = rep * 8 + gp8;
        uint32_t* dst = (uint32_t*)(smc + OFF_A + pp * APTB + gw * 4 * AROWB) + gkp;
        dst[0 * 12] = pack_f16x2(va.x, vb.x);
        dst[1 * 12] = pack_f16x2(va.y, vb.y);
        dst[2 * 12] = pack_f16x2(va.z, vb.z);
        dst[3 * 12] = pack_f16x2(va.w, vb.w);
    };

    __syncthreads();   // inds visible

    // ---- prologue gather: group 0 ----
    #pragma unroll
    for (int rep = 0; rep < 8; ++rep) {
        float4 va, vb;
        gatherLDG(0, rep, va, vb);
        gatherSTS(rep, va, vb);
    }

    // ---- Wfrag rolling prefetch slots: init with fs 0 and 1 ----
    const uint32_t* wfl = Wfrag + wn4 * 256 + l * 4;
    uint4 u[2][2];
    u[0][0] = *(const uint4*)wfl;
    u[0][1] = *(const uint4*)(wfl + 128);
    u[1][0] = *(const uint4*)(wfl + 1024);
    u[1][1] = *(const uint4*)(wfl + 1024 + 128);

    __syncthreads();   // A ready

    // role constants
    const int rr = l >> 2;
    const int mc = 2 * (l & 3);
    const uint32_t arow = smb + (uint32_t)((wm * 32 + (l & 15)) * PROWB
                                           + (l >> 4) * 16);
    const uint32_t aoff = (uint32_t)((l & 15) * AROWB + (l >> 4) * 16);

    auto mmaStep = [&](int s, const uint4& U0, const uint4& U1) {
        #pragma unroll
        for (int mt = 0; mt < 2; ++mt) {
            uint32_t a[4];
            ldsm4(a, arow + (uint32_t)(mt * 16 * PROWB + s * 32));
            mma16(acc[mt][0], a, U0.x, U0.y);
            mma16(acc[mt][1], a, U0.z, U0.w);
            mma16(acc[mt][2], a, U1.x, U1.y);
            mma16(acc[mt][3], a, U1.z, U1.w);
        }
    };

    for (int g = 0; g < 5; ++g) {
        // ---- pconv(g): per warp 8 points; 1 ldsm + 2 MMA + 4 STS ----
        #pragma unroll
        for (int j = 0; j < 8; ++j) {
            int ptl = wid * 8 + j;
            uint32_t a[4];
            ldsm4(a, smb + OFF_A + (uint32_t)(ptl * APTB) + aoff);
            char* prow = smc + OFF_P + ptl * PROWB;
            #pragma unroll
            for (int h = 0; h < 2; ++h) {
                float c[4] = {0.f, 0.f, 0.f, 0.f};
                mma16(c, a, bw[j][h][0], bw[j][h][1]);
                int fl = rr * 16 + h * 8 + mc;
                *(uint32_t*)(prow + fl * 2)         = pack_f16x2(c[0], c[1]);
                *(uint32_t*)(prow + (fl + 128) * 2) = pack_f16x2(c[2], c[3]);
            }
        }
        __syncthreads();   // P ready; A free

        const uint32_t* wfg = wfl + (size_t)(g * 16) * 1024;

        if (g < 4) {
            // ---- mainGEMM(g), 16 s-steps; gather(g+1) per 2-step block ----
            #pragma unroll
            for (int blk = 0; blk < 8; ++blk) {
                float4 va, vb;
                gatherLDG(g + 1, blk, va, vb);
                #pragma unroll
                for (int ss = 0; ss < 2; ++ss) {
                    int s = blk * 2 + ss;
                    // prefetch fs = g*16 + s + 2 (contiguous; crosses groups)
                    const uint32_t* wf2 = wfg + (size_t)(s + 2) * 1024;
                    uint4 p0 = *(const uint4*)wf2;
                    uint4 p1 = *(const uint4*)(wf2 + 128);
                    mmaStep(s, u[ss][0], u[ss][1]);
                    u[ss][0] = p0; u[ss][1] = p1;
                }
                gatherSTS(blk, va, vb);
            }
        } else {
            // ---- group 4: only 3 real s-steps (f < 1072) ----
            const uint32_t* wf2 = wfg + (size_t)2 * 1024;
            uint4 p0 = *(const uint4*)wf2;           // fs 66 (last real)
            uint4 p1 = *(const uint4*)(wf2 + 128);
            mmaStep(0, u[0][0], u[0][1]);
            mmaStep(1, u[1][0], u[1][1]);
            mmaStep(2, p0, p1);
        }
        __syncthreads();   // A(g+1) ready; P free
    }

    // ---- epilogue: bias + store (each warp 32p x 32o) ----
    #pragma unroll
    for (int mt = 0; mt < 2; ++mt) {
        int r = wm * 32 + mt * 16 + (l >> 2);
        #pragma unroll
        for (int nt = 0; nt < 4; ++nt) {
            int o  = wn4 * 32 + nt * 8 + 2 * (l & 3);
            float b0 = bsm[o], b1 = bsm[o + 1];
            int pid = base + r;
            *(float2*)(out + (size_t)pid * 128 + o) =
                make_float2(acc[mt][nt][0] + b0, acc[mt][nt][1] + b1);
            *(float2*)(out + (size_t)(pid + 8) * 128 + o) =
                make_float2(acc[mt][nt][2] + b0, acc[mt][nt][3] + b1);
        }
    }
}

extern "C" void kernel_launch(void* const* d_in, const int* in_sizes, int n_in,
                              void* d_out, int out_size) {
    const float* xin  = (const float*)d_in[0];
    const int*   nbr  = (const int*)d_in[1];
    const float* wng  = (const float*)d_in[2];
    const float* addf = (const float*)d_in[3];
    const float* W    = (const float*)d_in[4];
    const float* bias = (const float*)d_in[5];
    float*       out  = (float*)d_out;

    cudaFuncSetAttribute(pcl_kernel,
                         cudaFuncAttributeMaxDynamicSharedMemorySize, SMEM_BYTES);

    prep_kernel<<<80, 128>>>(W);
    pcl_kernel<<<GRID, THREADS, SMEM_BYTES>>>(xin, nbr, wng, addf, bias, out);
}